// round 15
// baseline (speedup 1.0000x reference)
#include <cuda_runtime.h>
#include <cuda_bf16.h>

// 4-qubit circuit, algebraically collapsed, TENSOR-CORE matvec:
//   init kernel (unchanged from R6): fixed 16x16 complex unitary U -> g_U.
//   main: per-warp batches of 32 samples: embed v (real, kron) -> smem;
//     Y = [Ur;Ui] V via mma.sync.m16n8k16 bf16 with split-bf16 precision
//     (AhBh + AhBl + AlBh, error ~1e-5); z = sign-weighted column sums of
//     |Y|^2 reduced across fragment lanes.
//
// R15 rationale: R6/R8/R9/R10/R14 establish a ~10us plateau for the fp32
// datapath (per-sample issue-slot cost invariant across occupancy, ILP,
// packing, and split variants). The 512 MAC/sample matvec moves to the
// tensor pipe; remaining fma/alu work is ~6 slots/sample.

#define N_QUBITS 4
#define N_LAYERS 6
#define N_AMPS   16
#define THREADS  128        // 4 warps
#define NWITER   2          // 32-sample batches per warp
#define WSAMP    (NWITER * 32)   // 64 samples per warp, 256 per block
#define VPAD     36         // smem sample-stride (bank-conflict-free reads)

__device__ float4 g_U[128];  // col i: float2 slots [i*16, i*16+16); m-th = U[m][i]

// ---------------- init: evolve 16 basis columns, shfl pair-exchange ----------------
__global__ void init_u_kernel(const float* __restrict__ w) {
    __shared__ float4 gm[N_LAYERS * N_QUBITS][2];
    int t = threadIdx.x;
    if (t < N_LAYERS * N_QUBITS) {
        float phi   = w[t * 3 + 0];
        float theta = w[t * 3 + 1];
        float omega = w[t * 3 + 2];
        float st, ct, sp, cp, sm, cm;
        __sincosf(theta * 0.5f, &st, &ct);
        __sincosf((phi + omega) * 0.5f, &sp, &cp);
        __sincosf((phi - omega) * 0.5f, &sm, &cm);
        gm[t][0] = make_float4( cp * ct, -sp * ct, -cm * st, -sm * st);
        gm[t][1] = make_float4( cm * st, -sm * st,  cp * ct,  sp * ct);
    }
    __syncthreads();

    int lane   = t & 31;
    int lane16 = lane & 15;
    int col    = (t >> 5) * 2 + (lane >> 4);
    float re = (lane16 == col) ? 1.0f : 0.0f;
    float im = 0.0f;

    #pragma unroll
    for (int l = 0; l < N_LAYERS; l++) {
        #pragma unroll
        for (int q = 0; q < N_QUBITS; q++) {
            int idx = l * N_QUBITS + q;
            float4 row0 = gm[idx][0];
            float4 row1 = gm[idx][1];
            const int stride = 8 >> q;
            int bit = lane16 & stride;
            float pre = __shfl_xor_sync(0xffffffffu, re, stride);
            float pim = __shfl_xor_sync(0xffffffffu, im, stride);
            float c0r = bit ? row1.x : row0.x,  c0i = bit ? row1.y : row0.y;
            float c1r = bit ? row1.z : row0.z,  c1i = bit ? row1.w : row0.w;
            float a0r = bit ? pre : re,  a0i = bit ? pim : im;
            float a1r = bit ? re : pre,  a1i = bit ? im : pim;
            float nre = c0r * a0r - c0i * a0i + c1r * a1r - c1i * a1i;
            float nim = c0r * a0i + c0i * a0r + c1r * a1i + c1i * a1r;
            re = nre; im = nim;
        }
        const int r = l % (N_QUBITS - 1) + 1;
        #pragma unroll
        for (int q = 0; q < N_QUBITS; q++) {
            const int cbit = 8 >> q, tbit = 8 >> ((q + r) % N_QUBITS);
            float pre = __shfl_xor_sync(0xffffffffu, re, tbit);
            float pim = __shfl_xor_sync(0xffffffffu, im, tbit);
            bool flip = (lane16 & cbit) != 0;
            re = flip ? pre : re;
            im = flip ? pim : im;
        }
    }
    float2* U = reinterpret_cast<float2*>(g_U);
    U[col * N_AMPS + lane16] = make_float2(re, im);
}

// ---------------- main ----------------
// split x into bf16 hi + bf16 lo, packed as bf16x2 (lo half = first element)
__device__ __forceinline__ void split2(float x0, float x1,
                                       unsigned& hi, unsigned& lo) {
    __nv_bfloat162 h = __floats2bfloat162_rn(x0, x1);   // .x = x0 (low half)
    hi = *reinterpret_cast<unsigned*>(&h);
    float r0 = __bfloat162float(h.x);
    float r1 = __bfloat162float(h.y);
    __nv_bfloat162 l = __floats2bfloat162_rn(x0 - r0, x1 - r1);
    lo = *reinterpret_cast<unsigned*>(&l);
}

#define MMA_BF16(C, A, B)                                                     \
    asm volatile(                                                             \
        "mma.sync.aligned.m16n8k16.row.col.f32.bf16.bf16.f32 "                \
        "{%0,%1,%2,%3}, {%4,%5,%6,%7}, {%8,%9}, {%0,%1,%2,%3};"               \
        : "+f"(C[0]), "+f"(C[1]), "+f"(C[2]), "+f"(C[3])                      \
        : "r"(A[0]), "r"(A[1]), "r"(A[2]), "r"(A[3]), "r"(B[0]), "r"(B[1]))

__global__ void __launch_bounds__(THREADS)
quantum_mma_kernel(const float* __restrict__ inputs,
                   float* __restrict__ out) {
    __shared__ float sUr[256], sUi[256];          // row-major [m][k]
    __shared__ float sV[4][16][VPAD];             // per-warp staged v, [k][sample]

    const int t = threadIdx.x;

    // load U (g_U is column-major: entry e = i*16+m)
    const float2* U2 = reinterpret_cast<const float2*>(g_U);
    #pragma unroll
    for (int e = t; e < 256; e += THREADS) {
        int i = e >> 4, m = e & 15;
        float2 u = U2[e];
        sUr[m * 16 + i] = u.x;
        sUi[m * 16 + i] = u.y;
    }
    __syncthreads();

    const int lane = t & 31, w = t >> 5;
    const int g = lane >> 2, tt = lane & 3;       // fragment coords

    // ---- A fragments (constant): rows {g, g+8}, ks {2tt,2tt+1, 2tt+8,2tt+9}
    // a0:(g,k0..k0+1) a1:(g+8,k0..) a2:(g,k0+8..) a3:(g+8,k0+8..)
    unsigned Arh[4], Arl[4], Aih[4], Ail[4];
    {
        const int rows[2] = {g, g + 8};
        const int kb[2]   = {2 * tt, 2 * tt + 8};
        #pragma unroll
        for (int ki = 0; ki < 2; ki++)
            #pragma unroll
            for (int ri = 0; ri < 2; ri++) {
                int idx = ri + ki * 2;
                int off = rows[ri] * 16 + kb[ki];
                split2(sUr[off], sUr[off + 1], Arh[idx], Arl[idx]);
                split2(sUi[off], sUi[off + 1], Aih[idx], Ail[idx]);
            }
    }

    const float s1 = (g & 4) ? -1.f : 1.f;        // z1 sign (row bit2)
    const float s2 = (g & 2) ? -1.f : 1.f;        // z2 sign (row bit1)
    const float s3 = (g & 1) ? -1.f : 1.f;        // z3 sign (row bit0)

    const int warpBase = (blockIdx.x * 4 + w) * WSAMP;
    const float4* in4 = reinterpret_cast<const float4*>(inputs);
    float4* out4 = reinterpret_cast<float4*>(out);

    #pragma unroll
    for (int it = 0; it < NWITER; it++) {
        const int S0 = warpBase + it * 32;

        // ---- embed: each lane one sample -> v[16] -> smem (transposed) ----
        {
            float4 x = in4[S0 + lane];
            float c0, s0f, c1, s1f, c2, s2f, c3, s3f;
            __sincosf(x.x * 0.5f, &s0f, &c0);
            __sincosf(x.y * 0.5f, &s1f, &c1);
            __sincosf(x.z * 0.5f, &s2f, &c2);
            __sincosf(x.w * 0.5f, &s3f, &c3);
            float P[4] = {c0 * c1, c0 * s1f, s0f * c1, s0f * s1f};
            float Q[4] = {c2 * c3, c2 * s3f, s2f * c3, s2f * s3f};
            #pragma unroll
            for (int k = 0; k < 16; k++)
                sV[w][k][lane] = P[k >> 2] * Q[k & 3];
        }
        __syncwarp();

        // ---- 4 groups of 8 samples ----
        #pragma unroll
        for (int grp = 0; grp < 4; grp++) {
            const int n = grp * 8 + g;            // this lane's B column/sample
            float b00 = sV[w][2 * tt][n],     b01 = sV[w][2 * tt + 1][n];
            float b10 = sV[w][2 * tt + 8][n], b11 = sV[w][2 * tt + 9][n];
            unsigned Bh[2], Bl[2];
            split2(b00, b01, Bh[0], Bl[0]);
            split2(b10, b11, Bh[1], Bl[1]);

            float Cre[4] = {0.f, 0.f, 0.f, 0.f};
            float Cim[4] = {0.f, 0.f, 0.f, 0.f};
            MMA_BF16(Cre, Arh, Bh);
            MMA_BF16(Cre, Arh, Bl);
            MMA_BF16(Cre, Arl, Bh);
            MMA_BF16(Cim, Aih, Bh);
            MMA_BF16(Cim, Aih, Bl);
            MMA_BF16(Cim, Ail, Bh);

            // ---- epilogue: p = |y|^2; per-lane partial z for 2 columns ----
            float p0 = Cre[0] * Cre[0] + Cim[0] * Cim[0];   // (row g,   col 2tt)
            float p1 = Cre[1] * Cre[1] + Cim[1] * Cim[1];   // (row g,   col 2tt+1)
            float p2 = Cre[2] * Cre[2] + Cim[2] * Cim[2];   // (row g+8, col 2tt)
            float p3 = Cre[3] * Cre[3] + Cim[3] * Cim[3];   // (row g+8, col 2tt+1)
            float d0 = p0 - p2, t0 = p0 + p2;               // col 2tt
            float d1 = p1 - p3, t1 = p1 + p3;               // col 2tt+1
            float z[8] = { d0, s1 * t0, s2 * t0, s3 * t0,
                           d1, s1 * t1, s2 * t1, s3 * t1 };
            #pragma unroll
            for (int r = 0; r < 8; r++) {
                z[r] += __shfl_xor_sync(0xffffffffu, z[r], 4);
                z[r] += __shfl_xor_sync(0xffffffffu, z[r], 8);
                z[r] += __shfl_xor_sync(0xffffffffu, z[r], 16);
            }
            if (g == 0) {
                out4[S0 + grp * 8 + 2 * tt]     = make_float4(z[0], z[1], z[2], z[3]);
                out4[S0 + grp * 8 + 2 * tt + 1] = make_float4(z[4], z[5], z[6], z[7]);
            }
        }
        __syncwarp();    // before next iteration overwrites sV
    }
}

extern "C" void kernel_launch(void* const* d_in, const int* in_sizes, int n_in,
                              void* d_out, int out_size) {
    const float* inputs  = (const float*)d_in[0];   // (B, 4) float32
    const float* weights = (const float*)d_in[1];   // (6, 4, 3) float32
    float* out = (float*)d_out;                     // (B, 4) float32
    int B = in_sizes[0] / N_QUBITS;

    init_u_kernel<<<1, 256>>>(weights);
    int blocks = B / (4 * WSAMP);                   // 262144 / 256 = 1024
    quantum_mma_kernel<<<blocks, THREADS>>>(inputs, out);
}

// round 16
// speedup vs baseline: 1.1429x; 1.1429x over previous
#include <cuda_runtime.h>
#include <cuda_bf16.h>

// 4-qubit circuit, algebraically collapsed, TENSOR-CORE matvec (R15 math):
//   init kernel: fixed 16x16 complex unitary U -> g_U (column-major float2).
//   main: warp batches of 32 samples; embed v (real kron) PRE-SPLIT into
//     bf16 hi/lo pairs in smem; Y = [Ur;Ui] V via mma.m16n8k16 bf16 with
//     split-bf16 (AhBh+AhBl+AlBh); z via multiplexed-butterfly reduction.
//
// R16 vs R15: (1) split2 moved to embed (consumer = LDS->MMA, no cvt chain),
// (2) epilogue 24 shfl -> 12 shfl multiplexed butterfly, 2 writer lanes,
// (3) A fragments built from L2-hot g_U directly (no smem staging pass).

#define N_QUBITS 4
#define N_LAYERS 6
#define N_AMPS   16
#define THREADS  128        // 4 warps
#define NWITER   2          // 32-sample batches per warp -> 64/warp, 256/block
#define VPAD     40         // smem sample stride: banks (8*tt+g) conflict-free

__device__ float4 g_U[128];  // col i: float2 slots [i*16, i*16+16); m-th = U[m][i]

// ---------------- init: evolve 16 basis columns, shfl pair-exchange ----------------
__global__ void init_u_kernel(const float* __restrict__ w) {
    __shared__ float4 gm[N_LAYERS * N_QUBITS][2];
    int t = threadIdx.x;
    if (t < N_LAYERS * N_QUBITS) {
        float phi   = w[t * 3 + 0];
        float theta = w[t * 3 + 1];
        float omega = w[t * 3 + 2];
        float st, ct, sp, cp, sm, cm;
        __sincosf(theta * 0.5f, &st, &ct);
        __sincosf((phi + omega) * 0.5f, &sp, &cp);
        __sincosf((phi - omega) * 0.5f, &sm, &cm);
        gm[t][0] = make_float4( cp * ct, -sp * ct, -cm * st, -sm * st);
        gm[t][1] = make_float4( cm * st, -sm * st,  cp * ct,  sp * ct);
    }
    __syncthreads();

    int lane   = t & 31;
    int lane16 = lane & 15;
    int col    = (t >> 5) * 2 + (lane >> 4);
    float re = (lane16 == col) ? 1.0f : 0.0f;
    float im = 0.0f;

    #pragma unroll
    for (int l = 0; l < N_LAYERS; l++) {
        #pragma unroll
        for (int q = 0; q < N_QUBITS; q++) {
            int idx = l * N_QUBITS + q;
            float4 row0 = gm[idx][0];
            float4 row1 = gm[idx][1];
            const int stride = 8 >> q;
            int bit = lane16 & stride;
            float pre = __shfl_xor_sync(0xffffffffu, re, stride);
            float pim = __shfl_xor_sync(0xffffffffu, im, stride);
            float c0r = bit ? row1.x : row0.x,  c0i = bit ? row1.y : row0.y;
            float c1r = bit ? row1.z : row0.z,  c1i = bit ? row1.w : row0.w;
            float a0r = bit ? pre : re,  a0i = bit ? pim : im;
            float a1r = bit ? re : pre,  a1i = bit ? im : pim;
            float nre = c0r * a0r - c0i * a0i + c1r * a1r - c1i * a1i;
            float nim = c0r * a0i + c0i * a0r + c1r * a1i + c1i * a1r;
            re = nre; im = nim;
        }
        const int r = l % (N_QUBITS - 1) + 1;
        #pragma unroll
        for (int q = 0; q < N_QUBITS; q++) {
            const int cbit = 8 >> q, tbit = 8 >> ((q + r) % N_QUBITS);
            float pre = __shfl_xor_sync(0xffffffffu, re, tbit);
            float pim = __shfl_xor_sync(0xffffffffu, im, tbit);
            bool flip = (lane16 & cbit) != 0;
            re = flip ? pre : re;
            im = flip ? pim : im;
        }
    }
    float2* U = reinterpret_cast<float2*>(g_U);
    U[col * N_AMPS + lane16] = make_float2(re, im);
}

// ---------------- main ----------------
// split (x0,x1) into bf16x2 hi + bf16x2 lo (x0 in the low half)
__device__ __forceinline__ void split2(float x0, float x1,
                                       unsigned& hi, unsigned& lo) {
    __nv_bfloat162 h = __floats2bfloat162_rn(x0, x1);
    hi = *reinterpret_cast<unsigned*>(&h);
    float r0 = __bfloat162float(h.x);
    float r1 = __bfloat162float(h.y);
    __nv_bfloat162 l = __floats2bfloat162_rn(x0 - r0, x1 - r1);
    lo = *reinterpret_cast<unsigned*>(&l);
}

#define MMA_BF16(C, A, B)                                                     \
    asm volatile(                                                             \
        "mma.sync.aligned.m16n8k16.row.col.f32.bf16.bf16.f32 "                \
        "{%0,%1,%2,%3}, {%4,%5,%6,%7}, {%8,%9}, {%0,%1,%2,%3};"               \
        : "+f"(C[0]), "+f"(C[1]), "+f"(C[2]), "+f"(C[3])                      \
        : "r"(A[0]), "r"(A[1]), "r"(A[2]), "r"(A[3]), "r"(B[0]), "r"(B[1]))

__global__ void __launch_bounds__(THREADS)
quantum_mma_kernel(const float* __restrict__ inputs,
                   float* __restrict__ out) {
    __shared__ unsigned sVh[4][8][VPAD];   // [warp][row-pair][sample]
    __shared__ unsigned sVl[4][8][VPAD];

    const int t = threadIdx.x;
    const int lane = t & 31, w = t >> 5;
    const int g = lane >> 2, tt = lane & 3;

    // ---- A fragments from g_U directly (one-time, L2-hot) ----
    // a-idx: 0:(g,2tt..) 1:(g+8,2tt..) 2:(g,2tt+8..) 3:(g+8,2tt+8..)
    unsigned Arh[4], Arl[4], Aih[4], Ail[4];
    {
        const float2* U2 = reinterpret_cast<const float2*>(g_U);
        const int rows[2] = {g, g + 8};
        const int kb[2]   = {2 * tt, 2 * tt + 8};
        #pragma unroll
        for (int ki = 0; ki < 2; ki++)
            #pragma unroll
            for (int ri = 0; ri < 2; ri++) {
                int idx = ri + ki * 2;
                float2 ua = __ldg(U2 + kb[ki] * 16 + rows[ri]);        // (k,   m)
                float2 ub = __ldg(U2 + (kb[ki] + 1) * 16 + rows[ri]);  // (k+1, m)
                split2(ua.x, ub.x, Arh[idx], Arl[idx]);
                split2(ua.y, ub.y, Aih[idx], Ail[idx]);
            }
    }

    const float s1 = (g & 4) ? -1.f : 1.f;        // wire1 sign (row bit2)
    const float s2 = (g & 2) ? -1.f : 1.f;        // wire2 sign (row bit1)
    const float s3 = (g & 1) ? -1.f : 1.f;        // wire3 sign (row bit0)
    const bool hi2 = (lane & 16) != 0;            // g bit2

    const int warpBase = (blockIdx.x * 4 + w) * (NWITER * 32);
    const float4* in4 = reinterpret_cast<const float4*>(inputs);
    float4* out4 = reinterpret_cast<float4*>(out);

    #pragma unroll
    for (int it = 0; it < NWITER; it++) {
        const int S0 = warpBase + it * 32;

        // ---- embed + pre-split: lane -> sample S0+lane ----
        {
            float4 x = in4[S0 + lane];
            float c0, s0f, c1, s1f, c2, s2f, c3, s3f;
            __sincosf(x.x * 0.5f, &s0f, &c0);
            __sincosf(x.y * 0.5f, &s1f, &c1);
            __sincosf(x.z * 0.5f, &s2f, &c2);
            __sincosf(x.w * 0.5f, &s3f, &c3);
            float P[4] = {c0 * c1, c0 * s1f, s0f * c1, s0f * s1f};
            float Q[4] = {c2 * c3, c2 * s3f, s2f * c3, s2f * s3f};
            #pragma unroll
            for (int j = 0; j < 8; j++) {
                float v0 = P[(2 * j) >> 2] * Q[(2 * j) & 3];
                float v1 = P[(2 * j + 1) >> 2] * Q[(2 * j + 1) & 3];
                unsigned hi, lo;
                split2(v0, v1, hi, lo);
                sVh[w][j][lane] = hi;
                sVl[w][j][lane] = lo;
            }
        }
        __syncwarp();

        // ---- 4 groups of 8 samples ----
        #pragma unroll
        for (int grp = 0; grp < 4; grp++) {
            const int n = grp * 8 + g;
            unsigned Bh[2] = { sVh[w][tt][n], sVh[w][tt + 4][n] };
            unsigned Bl[2] = { sVl[w][tt][n], sVl[w][tt + 4][n] };

            float Cre[4] = {0.f, 0.f, 0.f, 0.f};
            float Cim[4] = {0.f, 0.f, 0.f, 0.f};
            MMA_BF16(Cre, Arh, Bh);
            MMA_BF16(Cre, Arh, Bl);
            MMA_BF16(Cre, Arl, Bh);
            MMA_BF16(Cim, Aih, Bh);
            MMA_BF16(Cim, Aih, Bl);
            MMA_BF16(Cim, Ail, Bh);

            // ---- epilogue ----
            float p0 = Cre[0] * Cre[0] + Cim[0] * Cim[0];   // (g,   2tt)
            float p1 = Cre[1] * Cre[1] + Cim[1] * Cim[1];   // (g,   2tt+1)
            float p2 = Cre[2] * Cre[2] + Cim[2] * Cim[2];   // (g+8, 2tt)
            float p3 = Cre[3] * Cre[3] + Cim[3] * Cim[3];   // (g+8, 2tt+1)
            float d0 = p0 - p2, t0 = p0 + p2;               // col 2tt
            float d1 = p1 - p3, t1 = p1 + p3;               // col 2tt+1
            float z[8] = { d0, s1 * t0, s2 * t0, s3 * t0,
                           d1, s1 * t1, s2 * t1, s3 * t1 };

            // multiplexed butterfly over the 8 g-lanes:
            // round 1 (mask 16): exchange component halves; then plain 8,4.
            float wz[4];
            #pragma unroll
            for (int i = 0; i < 4; i++) {
                float send = hi2 ? z[i] : z[i + 4];
                float recv = __shfl_xor_sync(0xffffffffu, send, 16);
                float keep = hi2 ? z[i + 4] : z[i];
                wz[i] = keep + recv;
            }
            #pragma unroll
            for (int i = 0; i < 4; i++)
                wz[i] += __shfl_xor_sync(0xffffffffu, wz[i], 8);
            #pragma unroll
            for (int i = 0; i < 4; i++)
                wz[i] += __shfl_xor_sync(0xffffffffu, wz[i], 4);

            // lanes with g&3==0 hold full sums: g=0 -> col 2tt, g=4 -> col 2tt+1
            if ((lane & 12) == 0)
                out4[S0 + grp * 8 + 2 * tt + (hi2 ? 1 : 0)] =
                    make_float4(wz[0], wz[1], wz[2], wz[3]);
        }
        __syncwarp();    // before next iteration overwrites sV
    }
}

extern "C" void kernel_launch(void* const* d_in, const int* in_sizes, int n_in,
                              void* d_out, int out_size) {
    const float* inputs  = (const float*)d_in[0];   // (B, 4) float32
    const float* weights = (const float*)d_in[1];   // (6, 4, 3) float32
    float* out = (float*)d_out;                     // (B, 4) float32
    int B = in_sizes[0] / N_QUBITS;

    init_u_kernel<<<1, 256>>>(weights);
    int blocks = B / (4 * NWITER * 32);             // 262144 / 256 = 1024
    quantum_mma_kernel<<<blocks, THREADS>>>(inputs, out);
}

// round 17
// speedup vs baseline: 1.1600x; 1.0150x over previous
#include <cuda_runtime.h>
#include <cuda_bf16.h>

// 4-qubit circuit, algebraically collapsed, TENSOR-CORE matvec (R15/R16 math):
//   init kernel: fixed 16x16 complex unitary U -> g_U (column-major float2).
//   main: warp batches of 32 samples; embed v (real kron) pre-split into
//     bf16 hi/lo pairs in smem; Y = [Ur;Ui] V via mma.m16n8k16 bf16.
//
// R17 vs R16: ILP restructure. R16 ran at regs=53 -> ptxas serialized the
// 3-deep MMA accumulator chains and shfl rounds (~170 exposed-latency cyc
// per 8-sample group). Now: (1) split accumulators Ca=AhBh / Cb=AhBl+AlBh
// -> 16 independent 1-2 deep chains across 4 groups issued together,
// (2) epilogue butterfly rounds batched across all 4 groups,
// (3) launch_bounds(128,3) -> 170-reg budget so the ~110-reg live set stays
// in registers.

#define N_QUBITS 4
#define N_LAYERS 6
#define N_AMPS   16
#define THREADS  128        // 4 warps
#define NWITER   2          // 32-sample batches per warp -> 64/warp, 256/block
#define VPAD     40         // smem sample stride: banks (8*tt+g) conflict-free

__device__ float4 g_U[128];  // col i: float2 slots [i*16, i*16+16); m-th = U[m][i]

// ---------------- init: evolve 16 basis columns, shfl pair-exchange ----------------
__global__ void init_u_kernel(const float* __restrict__ w) {
    __shared__ float4 gm[N_LAYERS * N_QUBITS][2];
    int t = threadIdx.x;
    if (t < N_LAYERS * N_QUBITS) {
        float phi   = w[t * 3 + 0];
        float theta = w[t * 3 + 1];
        float omega = w[t * 3 + 2];
        float st, ct, sp, cp, sm, cm;
        __sincosf(theta * 0.5f, &st, &ct);
        __sincosf((phi + omega) * 0.5f, &sp, &cp);
        __sincosf((phi - omega) * 0.5f, &sm, &cm);
        gm[t][0] = make_float4( cp * ct, -sp * ct, -cm * st, -sm * st);
        gm[t][1] = make_float4( cm * st, -sm * st,  cp * ct,  sp * ct);
    }
    __syncthreads();

    int lane   = t & 31;
    int lane16 = lane & 15;
    int col    = (t >> 5) * 2 + (lane >> 4);
    float re = (lane16 == col) ? 1.0f : 0.0f;
    float im = 0.0f;

    #pragma unroll
    for (int l = 0; l < N_LAYERS; l++) {
        #pragma unroll
        for (int q = 0; q < N_QUBITS; q++) {
            int idx = l * N_QUBITS + q;
            float4 row0 = gm[idx][0];
            float4 row1 = gm[idx][1];
            const int stride = 8 >> q;
            int bit = lane16 & stride;
            float pre = __shfl_xor_sync(0xffffffffu, re, stride);
            float pim = __shfl_xor_sync(0xffffffffu, im, stride);
            float c0r = bit ? row1.x : row0.x,  c0i = bit ? row1.y : row0.y;
            float c1r = bit ? row1.z : row0.z,  c1i = bit ? row1.w : row0.w;
            float a0r = bit ? pre : re,  a0i = bit ? pim : im;
            float a1r = bit ? re : pre,  a1i = bit ? im : pim;
            float nre = c0r * a0r - c0i * a0i + c1r * a1r - c1i * a1i;
            float nim = c0r * a0i + c0i * a0r + c1r * a1i + c1i * a1r;
            re = nre; im = nim;
        }
        const int r = l % (N_QUBITS - 1) + 1;
        #pragma unroll
        for (int q = 0; q < N_QUBITS; q++) {
            const int cbit = 8 >> q, tbit = 8 >> ((q + r) % N_QUBITS);
            float pre = __shfl_xor_sync(0xffffffffu, re, tbit);
            float pim = __shfl_xor_sync(0xffffffffu, im, tbit);
            bool flip = (lane16 & cbit) != 0;
            re = flip ? pre : re;
            im = flip ? pim : im;
        }
    }
    float2* U = reinterpret_cast<float2*>(g_U);
    U[col * N_AMPS + lane16] = make_float2(re, im);
}

// ---------------- main ----------------
__device__ __forceinline__ void split2(float x0, float x1,
                                       unsigned& hi, unsigned& lo) {
    __nv_bfloat162 h = __floats2bfloat162_rn(x0, x1);
    hi = *reinterpret_cast<unsigned*>(&h);
    float r0 = __bfloat162float(h.x);
    float r1 = __bfloat162float(h.y);
    __nv_bfloat162 l = __floats2bfloat162_rn(x0 - r0, x1 - r1);
    lo = *reinterpret_cast<unsigned*>(&l);
}

#define MMA_BF16(C, A, B)                                                     \
    asm volatile(                                                             \
        "mma.sync.aligned.m16n8k16.row.col.f32.bf16.bf16.f32 "                \
        "{%0,%1,%2,%3}, {%4,%5,%6,%7}, {%8,%9}, {%0,%1,%2,%3};"               \
        : "+f"(C[0]), "+f"(C[1]), "+f"(C[2]), "+f"(C[3])                      \
        : "r"(A[0]), "r"(A[1]), "r"(A[2]), "r"(A[3]), "r"(B[0]), "r"(B[1]))

__global__ void __launch_bounds__(THREADS, 3)
quantum_mma_kernel(const float* __restrict__ inputs,
                   float* __restrict__ out) {
    __shared__ unsigned sVh[4][8][VPAD];   // [warp][row-pair][sample]
    __shared__ unsigned sVl[4][8][VPAD];

    const int t = threadIdx.x;
    const int lane = t & 31, w = t >> 5;
    const int g = lane >> 2, tt = lane & 3;

    // ---- A fragments from g_U directly (one-time, L2-hot) ----
    unsigned Arh[4], Arl[4], Aih[4], Ail[4];
    {
        const float2* U2 = reinterpret_cast<const float2*>(g_U);
        const int rows[2] = {g, g + 8};
        const int kb[2]   = {2 * tt, 2 * tt + 8};
        #pragma unroll
        for (int ki = 0; ki < 2; ki++)
            #pragma unroll
            for (int ri = 0; ri < 2; ri++) {
                int idx = ri + ki * 2;
                float2 ua = __ldg(U2 + kb[ki] * 16 + rows[ri]);
                float2 ub = __ldg(U2 + (kb[ki] + 1) * 16 + rows[ri]);
                split2(ua.x, ub.x, Arh[idx], Arl[idx]);
                split2(ua.y, ub.y, Aih[idx], Ail[idx]);
            }
    }

    const float s1 = (g & 4) ? -1.f : 1.f;
    const float s2 = (g & 2) ? -1.f : 1.f;
    const float s3 = (g & 1) ? -1.f : 1.f;
    const bool hi2 = (lane & 16) != 0;

    const int warpBase = (blockIdx.x * 4 + w) * (NWITER * 32);
    const float4* in4 = reinterpret_cast<const float4*>(inputs);
    float4* out4 = reinterpret_cast<float4*>(out);

    #pragma unroll
    for (int it = 0; it < NWITER; it++) {
        const int S0 = warpBase + it * 32;

        // ---- embed + pre-split: lane -> sample S0+lane ----
        {
            float4 x = in4[S0 + lane];
            float c0, s0f, c1, s1f, c2, s2f, c3, s3f;
            __sincosf(x.x * 0.5f, &s0f, &c0);
            __sincosf(x.y * 0.5f, &s1f, &c1);
            __sincosf(x.z * 0.5f, &s2f, &c2);
            __sincosf(x.w * 0.5f, &s3f, &c3);
            float P[4] = {c0 * c1, c0 * s1f, s0f * c1, s0f * s1f};
            float Q[4] = {c2 * c3, c2 * s3f, s2f * c3, s2f * s3f};
            #pragma unroll
            for (int j = 0; j < 8; j++) {
                float v0 = P[(2 * j) >> 2] * Q[(2 * j) & 3];
                float v1 = P[(2 * j + 1) >> 2] * Q[(2 * j + 1) & 3];
                unsigned hi, lo;
                split2(v0, v1, hi, lo);
                sVh[w][j][lane] = hi;
                sVl[w][j][lane] = lo;
            }
        }
        __syncwarp();

        // ---- stage 1: all 4 groups' B loads + 24 MMAs, split accumulators ----
        unsigned Bh[4][2], Bl[4][2];
        #pragma unroll
        for (int grp = 0; grp < 4; grp++) {
            const int n = grp * 8 + g;
            Bh[grp][0] = sVh[w][tt][n];     Bh[grp][1] = sVh[w][tt + 4][n];
            Bl[grp][0] = sVl[w][tt][n];     Bl[grp][1] = sVl[w][tt + 4][n];
        }

        float Car[4][4], Cbr[4][4], Cai[4][4], Cbi[4][4];
        #pragma unroll
        for (int grp = 0; grp < 4; grp++)
            #pragma unroll
            for (int c = 0; c < 4; c++) {
                Car[grp][c] = 0.f; Cbr[grp][c] = 0.f;
                Cai[grp][c] = 0.f; Cbi[grp][c] = 0.f;
            }

        // 1-deep chains: Ca = Ah*Bh (4 re + 4 im independent)
        #pragma unroll
        for (int grp = 0; grp < 4; grp++) {
            MMA_BF16(Car[grp], Arh, Bh[grp]);
            MMA_BF16(Cai[grp], Aih, Bh[grp]);
        }
        // 2-deep chains: Cb = Ah*Bl + Al*Bh (4 re + 4 im independent)
        #pragma unroll
        for (int grp = 0; grp < 4; grp++) {
            MMA_BF16(Cbr[grp], Arh, Bl[grp]);
            MMA_BF16(Cbi[grp], Aih, Bl[grp]);
        }
        #pragma unroll
        for (int grp = 0; grp < 4; grp++) {
            MMA_BF16(Cbr[grp], Arl, Bh[grp]);
            MMA_BF16(Cbi[grp], Ail, Bh[grp]);
        }

        // ---- stage 2: per-group partials, then batched butterfly rounds ----
        float wz[4][4];
        #pragma unroll
        for (int grp = 0; grp < 4; grp++) {
            float yr0 = Car[grp][0] + Cbr[grp][0], yi0 = Cai[grp][0] + Cbi[grp][0];
            float yr1 = Car[grp][1] + Cbr[grp][1], yi1 = Cai[grp][1] + Cbi[grp][1];
            float yr2 = Car[grp][2] + Cbr[grp][2], yi2 = Cai[grp][2] + Cbi[grp][2];
            float yr3 = Car[grp][3] + Cbr[grp][3], yi3 = Cai[grp][3] + Cbi[grp][3];
            float p0 = yr0 * yr0 + yi0 * yi0;   // (g,   2tt)
            float p1 = yr1 * yr1 + yi1 * yi1;   // (g,   2tt+1)
            float p2 = yr2 * yr2 + yi2 * yi2;   // (g+8, 2tt)
            float p3 = yr3 * yr3 + yi3 * yi3;   // (g+8, 2tt+1)
            float d0 = p0 - p2, t0 = p0 + p2;
            float d1 = p1 - p3, t1 = p1 + p3;
            float z[8] = { d0, s1 * t0, s2 * t0, s3 * t0,
                           d1, s1 * t1, s2 * t1, s3 * t1 };
            // mux round (mask 16): exchange halves
            #pragma unroll
            for (int i = 0; i < 4; i++) {
                float send = hi2 ? z[i] : z[i + 4];
                float recv = __shfl_xor_sync(0xffffffffu, send, 16);
                float keep = hi2 ? z[i + 4] : z[i];
                wz[grp][i] = keep + recv;
            }
        }
        // rounds 8 and 4: 16 independent shfl streams each
        #pragma unroll
        for (int grp = 0; grp < 4; grp++)
            #pragma unroll
            for (int i = 0; i < 4; i++)
                wz[grp][i] += __shfl_xor_sync(0xffffffffu, wz[grp][i], 8);
        #pragma unroll
        for (int grp = 0; grp < 4; grp++)
            #pragma unroll
            for (int i = 0; i < 4; i++)
                wz[grp][i] += __shfl_xor_sync(0xffffffffu, wz[grp][i], 4);

        #pragma unroll
        for (int grp = 0; grp < 4; grp++)
            if ((lane & 12) == 0)
                out4[S0 + grp * 8 + 2 * tt + (hi2 ? 1 : 0)] =
                    make_float4(wz[grp][0], wz[grp][1], wz[grp][2], wz[grp][3]);

        __syncwarp();    // before next iteration overwrites sV
    }
}

extern "C" void kernel_launch(void* const* d_in, const int* in_sizes, int n_in,
                              void* d_out, int out_size) {
    const float* inputs  = (const float*)d_in[0];   // (B, 4) float32
    const float* weights = (const float*)d_in[1];   // (6, 4, 3) float32
    float* out = (float*)d_out;                     // (B, 4) float32
    int B = in_sizes[0] / N_QUBITS;

    init_u_kernel<<<1, 256>>>(weights);
    int blocks = B / (4 * NWITER * 32);             // 262144 / 256 = 1024
    quantum_mma_kernel<<<blocks, THREADS>>>(inputs, out);
}